// round 10
// baseline (speedup 1.0000x reference)
#include <cuda_runtime.h>
#include <cuda_fp16.h>
#include <cstdint>
#include <cstddef>

#define NN 170000
#define NE 1200000
#define NBLK_SCAN 167        // ceil(NN / 1024)
#define CSR_CAP 2600000      // >= NE + 7*NN (padded edge list capacity)

// ---------------- device scratch (allocation-free) ----------------
__device__ __half g_G[(size_t)(NN + 1) * 128];  // +1: dummy zero row (128-wide index NN)
__device__ __half g_H[(size_t)NN * 128];        // GEMM A source (fp16)
__device__ int    g_deg_out[NN];
__device__ int    g_cnt[NN];
__device__ int    g_off[NN];                    // padded CSR offsets
__device__ int2   g_meta[NN];                   // {padded offset, padded count}
__device__ int    g_fill[NN];
__device__ int    g_bsum[NBLK_SCAN];
__device__ float  g_norm_out[NN];
__device__ float  g_norm_in[NN];
__device__ int    g_csr_src[CSR_CAP];

// ---------------- CSR build ----------------
__global__ void zero_kernel() {
    int i = blockIdx.x * blockDim.x + threadIdx.x;
    if (i < NN) { g_deg_out[i] = 0; g_cnt[i] = 0; g_fill[i] = 0; }
}

__global__ void hist_kernel(const int* __restrict__ src, const int* __restrict__ dst) {
    int e = blockIdx.x * blockDim.x + threadIdx.x;
    if (e < NE) {
        atomicAdd(&g_deg_out[src[e]], 1);
        atomicAdd(&g_cnt[dst[e]], 1);
    }
}

// norms + feat*norm_out -> g_H (fp16), fused (keeps GEMM0 at launch slot #4)
__global__ void norm_conv_kernel(const float* __restrict__ X) {
    int i = blockIdx.x * blockDim.x + threadIdx.x;   // over NN*32 float4s
    if (i >= NN * 32) return;
    const int row = i >> 5;
    int din  = g_cnt[row];     if (din  < 1) din  = 1;
    int dout = g_deg_out[row]; if (dout < 1) dout = 1;
    const float no = rsqrtf((float)dout);
    if ((i & 31) == 0) {
        g_norm_in[row]  = rsqrtf((float)din);
        g_norm_out[row] = no;
    }
    float4 v = reinterpret_cast<const float4*>(X)[i];
    __half2 h0 = __floats2half2_rn(v.x * no, v.y * no);
    __half2 h1 = __floats2half2_rn(v.z * no, v.w * no);
    uint2 o;
    o.x = *reinterpret_cast<uint32_t*>(&h0);
    o.y = *reinterpret_cast<uint32_t*>(&h1);
    reinterpret_cast<uint2*>(g_H)[i] = o;
}

__global__ void fill_kernel() {   // pre-fill padded edge list with dummy index NN
    int i = blockIdx.x * blockDim.x + threadIdx.x;
    if (i < CSR_CAP / 4) reinterpret_cast<int4*>(g_csr_src)[i] = make_int4(NN, NN, NN, NN);
}

__global__ void scan1_kernel() {  // scan padded counts
    __shared__ int sh[256];
    const int t = threadIdx.x;
    const int base = blockIdx.x * 1024 + t * 4;
    int c0 = 0, c1 = 0, c2 = 0, c3 = 0;
    if (base + 3 < NN) {
        int4 v = *reinterpret_cast<const int4*>(&g_cnt[base]);
        c0 = v.x; c1 = v.y; c2 = v.z; c3 = v.w;
    } else {
        if (base     < NN) c0 = g_cnt[base];
        if (base + 1 < NN) c1 = g_cnt[base + 1];
        if (base + 2 < NN) c2 = g_cnt[base + 2];
        if (base + 3 < NN) c3 = g_cnt[base + 3];
    }
    c0 = (c0 + 7) & ~7; c1 = (c1 + 7) & ~7; c2 = (c2 + 7) & ~7; c3 = (c3 + 7) & ~7;
    const int mysum = c0 + c1 + c2 + c3;
    sh[t] = mysum;
    __syncthreads();
    for (int off = 1; off < 256; off <<= 1) {
        int v = (t >= off) ? sh[t - off] : 0;
        __syncthreads();
        sh[t] += v;
        __syncthreads();
    }
    const int excl = sh[t] - mysum;
    if (t == 255) g_bsum[blockIdx.x] = sh[255];
    if (base     < NN) g_off[base]     = excl;
    if (base + 1 < NN) g_off[base + 1] = excl + c0;
    if (base + 2 < NN) g_off[base + 2] = excl + c0 + c1;
    if (base + 3 < NN) g_off[base + 3] = excl + c0 + c1 + c2;
}

__global__ void scan2_kernel() {
    __shared__ int sh[256];
    const int t = threadIdx.x;
    int v = (t < NBLK_SCAN) ? g_bsum[t] : 0;
    sh[t] = v;
    __syncthreads();
    for (int off = 1; off < 256; off <<= 1) {
        int u = (t >= off) ? sh[t - off] : 0;
        __syncthreads();
        sh[t] += u;
        __syncthreads();
    }
    if (t < NBLK_SCAN) g_bsum[t] = sh[t] - v;
}

__global__ void scan3_kernel() {   // finalize offsets + meta
    int i = blockIdx.x * blockDim.x + threadIdx.x;
    if (i < NN) {
        const int off = g_off[i] + g_bsum[i >> 10];
        g_off[i] = off;
        g_meta[i] = make_int2(off, (g_cnt[i] + 7) & ~7);
    }
}

__global__ void place_kernel(const int* __restrict__ src, const int* __restrict__ dst) {
    int e = blockIdx.x * blockDim.x + threadIdx.x;
    if (e < NE) {
        const int d = dst[e];
        const int pos = g_off[d] + atomicAdd(&g_fill[d], 1);
        g_csr_src[pos] = src[e];
    }
}

// ---------------- mma / ldmatrix / cp.async helpers ----------------
__device__ __forceinline__ void mma_f16(float* c, const uint32_t* a, uint32_t b0, uint32_t b1) {
    asm volatile(
        "mma.sync.aligned.m16n8k16.row.col.f32.f16.f16.f32 "
        "{%0,%1,%2,%3}, {%4,%5,%6,%7}, {%8,%9}, {%0,%1,%2,%3};"
        : "+f"(c[0]), "+f"(c[1]), "+f"(c[2]), "+f"(c[3])
        : "r"(a[0]), "r"(a[1]), "r"(a[2]), "r"(a[3]), "r"(b0), "r"(b1));
}

__device__ __forceinline__ void ldsm_x4(uint32_t* r, uint32_t addr) {
    asm volatile("ldmatrix.sync.aligned.m8n8.x4.shared.b16 {%0,%1,%2,%3}, [%4];"
                 : "=r"(r[0]), "=r"(r[1]), "=r"(r[2]), "=r"(r[3]) : "r"(addr));
}

__device__ __forceinline__ void ldsm_x2(uint32_t& r0, uint32_t& r1, uint32_t addr) {
    asm volatile("ldmatrix.sync.aligned.m8n8.x2.shared.b16 {%0,%1}, [%2];"
                 : "=r"(r0), "=r"(r1) : "r"(addr));
}

__device__ __forceinline__ void cp16(uint32_t dst, const void* src) {
    asm volatile("cp.async.cg.shared.global [%0], [%1], 16;" :: "r"(dst), "l"(src));
}
__device__ __forceinline__ void cp_commit() { asm volatile("cp.async.commit_group;"); }
__device__ __forceinline__ void cp_wait1()  { asm volatile("cp.async.wait_group 1;"); }

// ---------------- tensor-core GEMM (fp16 + ldmatrix + cp.async double buffer) ----------------
// A always from g_H (fp16). Smem word stride P=68 (68%32==4 => ldmatrix conflict-free).
template <int OUTD>
__global__ void __launch_bounds__(256, 3) mma_gemm(const float* __restrict__ W) {
    constexpr int NF = OUTD / 32;
    constexpr int P  = 68;
    extern __shared__ uint32_t smw[];
    uint32_t* Wh = smw;                    // [OUTD][P]
    uint32_t* A0 = Wh + OUTD * P;          // [64][P] buffer 0
    uint32_t* A1 = A0 + 64 * P;            // [64][P] buffer 1

    const int tid  = threadIdx.x;
    const int lane = tid & 31;
    const int warp = tid >> 5;
    const int mw   = warp & 1;
    const int nw   = warp >> 1;
    const int g    = lane >> 2;
    const int tg   = lane & 3;

    // 64-wide dummy row (index NN in 64-wide layout) must be zero; that memory
    // holds stale 128-wide data, so GEMM<64> re-zeroes it each launch.
    if (OUTD == 64 && blockIdx.x == 0 && tid < 32)
        reinterpret_cast<uint32_t*>(g_G + (size_t)NN * 64)[tid] = 0u;

    // W -> smem, transposed [n][k], fp16 pairs
    for (int i = tid; i < 64 * OUTD; i += 256) {
        const int kp = i / OUTD, n = i - kp * OUTD;
        const float w0 = W[(size_t)(kp * 2)     * OUTD + n];
        const float w1 = W[(size_t)(kp * 2 + 1) * OUTD + n];
        __half2 h = __floats2half2_rn(w0, w1);
        Wh[n * P + kp] = *reinterpret_cast<uint32_t*>(&h);
    }

    const uint32_t aB0 = (uint32_t)__cvta_generic_to_shared(A0);
    const uint32_t aB1 = (uint32_t)__cvta_generic_to_shared(A1);
    const uint32_t wBase = (uint32_t)__cvta_generic_to_shared(Wh);
    const int sel = lane >> 3;
    const int li  = lane & 7;
    uint32_t aOff[2];
#pragma unroll
    for (int mf = 0; mf < 2; mf++) {
        const int row = mw * 32 + mf * 16 + (sel & 1) * 8 + li;
        aOff[mf] = (uint32_t)((row * P + (sel >> 1) * 4) * 4);
    }
    uint32_t bAddr[NF];
#pragma unroll
    for (int nf = 0; nf < NF; nf++) {
        const int n = nw * (NF * 8) + nf * 8 + li;
        bAddr[nf] = wBase + (uint32_t)((n * P + (sel & 1) * 4) * 4);
    }

    // per-thread cp.async chunks: 4 x 16B per tile
    auto prefetch = [&](int tile, uint32_t bufBase) {
#pragma unroll
        for (int j = 0; j < 4; j++) {
            const int id = tid + j * 256;
            const int r = id >> 4, c16 = id & 15;
            int row = tile * 64 + r;
            if (row >= NN) row = NN - 1;   // clamp; results for rows>=NN never stored
            cp16(bufBase + (uint32_t)((r * P + c16 * 4) * 4),
                 g_H + (size_t)row * 128 + c16 * 8);
        }
    };

    const int ntiles = (NN + 63) / 64;
    int t = blockIdx.x;
    if (t < ntiles) prefetch(t, aB0);
    cp_commit();
    int parity = 0;

    for (; t < ntiles; t += gridDim.x) {
        const int tn = t + gridDim.x;
        if (tn < ntiles) prefetch(tn, parity ? aB0 : aB1);
        cp_commit();
        cp_wait1();
        __syncthreads();
        const uint32_t aBase = parity ? aB1 : aB0;

        float acc[2][NF][4];
#pragma unroll
        for (int mf = 0; mf < 2; mf++)
#pragma unroll
            for (int nf = 0; nf < NF; nf++)
#pragma unroll
                for (int j = 0; j < 4; j++) acc[mf][nf][j] = 0.f;

#pragma unroll
        for (int ks = 0; ks < 8; ks++) {
            uint32_t a[2][4];
            ldsm_x4(a[0], aBase + aOff[0] + ks * 32);
            ldsm_x4(a[1], aBase + aOff[1] + ks * 32);
            uint32_t b[NF][2];
#pragma unroll
            for (int nf = 0; nf < NF; nf++)
                ldsm_x2(b[nf][0], b[nf][1], bAddr[nf] + ks * 32);
#pragma unroll
            for (int nf = 0; nf < NF; nf++)
#pragma unroll
                for (int mf = 0; mf < 2; mf++)
                    mma_f16(acc[mf][nf], a[mf], b[nf][0], b[nf][1]);
        }

        const int rowbase = t * 64;
#pragma unroll
        for (int mf = 0; mf < 2; mf++) {
            const int r0 = rowbase + mw * 32 + mf * 16 + g;
#pragma unroll
            for (int nf = 0; nf < NF; nf++) {
                const int col = nw * (NF * 8) + nf * 8 + tg * 2;
                if (r0 < NN) {
                    __half2 h = __floats2half2_rn(acc[mf][nf][0], acc[mf][nf][1]);
                    *reinterpret_cast<__half2*>(&g_G[(size_t)r0 * OUTD + col]) = h;
                }
                if (r0 + 8 < NN) {
                    __half2 h = __floats2half2_rn(acc[mf][nf][2], acc[mf][nf][3]);
                    *reinterpret_cast<__half2*>(&g_G[(size_t)(r0 + 8) * OUTD + col]) = h;
                }
            }
        }
        __syncthreads();
        parity ^= 1;
    }
}

// ---------------- padded-CSR gather aggregation: half-warp per node, unpredicated ----------------
template <int WIDTH, bool FINAL>
__global__ void __launch_bounds__(256) agg_kernel(const float* __restrict__ bias,
                                                  float* __restrict__ outp) {
    const int l   = threadIdx.x & 15;
    const int ghw = (blockIdx.x * blockDim.x + threadIdx.x) >> 4;
    const int nhw = (gridDim.x * blockDim.x) >> 4;

    for (int n = ghw; n < NN; n += nhw) {
        const int2 meta = __ldg(&g_meta[n]);
        const int beg = meta.x;
        const int pend = meta.x + meta.y;

        if (WIDTH == 128) {
            float accA[8] = {0,0,0,0,0,0,0,0};
            float accB[8] = {0,0,0,0,0,0,0,0};
            for (int e = beg; e < pend; e += 8) {
                const int4 i0 = __ldg(reinterpret_cast<const int4*>(&g_csr_src[e]));
                const int4 i1 = __ldg(reinterpret_cast<const int4*>(&g_csr_src[e + 4]));
                const int idx[8] = {i0.x, i0.y, i0.z, i0.w, i1.x, i1.y, i1.z, i1.w};
                uint4 raw[8];
#pragma unroll
                for (int m = 0; m < 8; m++)
                    raw[m] = reinterpret_cast<const uint4*>(g_G + (size_t)idx[m] * 128)[l];
#pragma unroll
                for (int m = 0; m < 8; m++) {
                    float* acc = (m & 1) ? accB : accA;
                    const float2 p0 = __half22float2(*reinterpret_cast<const __half2*>(&raw[m].x));
                    const float2 p1 = __half22float2(*reinterpret_cast<const __half2*>(&raw[m].y));
                    const float2 p2 = __half22float2(*reinterpret_cast<const __half2*>(&raw[m].z));
                    const float2 p3 = __half22float2(*reinterpret_cast<const __half2*>(&raw[m].w));
                    acc[0] += p0.x; acc[1] += p0.y; acc[2] += p1.x; acc[3] += p1.y;
                    acc[4] += p2.x; acc[5] += p2.y; acc[6] += p3.x; acc[7] += p3.y;
                }
            }
            const float ni = g_norm_in[n];
            const float no = g_norm_out[n];
            const float4 bb0 = reinterpret_cast<const float4*>(bias)[l * 2];
            const float4 bb1 = reinterpret_cast<const float4*>(bias)[l * 2 + 1];
            float r0 = fmaxf(fmaf(accA[0] + accB[0], ni, bb0.x), 0.f) * no;
            float r1 = fmaxf(fmaf(accA[1] + accB[1], ni, bb0.y), 0.f) * no;
            float r2 = fmaxf(fmaf(accA[2] + accB[2], ni, bb0.z), 0.f) * no;
            float r3 = fmaxf(fmaf(accA[3] + accB[3], ni, bb0.w), 0.f) * no;
            float r4 = fmaxf(fmaf(accA[4] + accB[4], ni, bb1.x), 0.f) * no;
            float r5 = fmaxf(fmaf(accA[5] + accB[5], ni, bb1.y), 0.f) * no;
            float r6 = fmaxf(fmaf(accA[6] + accB[6], ni, bb1.z), 0.f) * no;
            float r7 = fmaxf(fmaf(accA[7] + accB[7], ni, bb1.w), 0.f) * no;
            __half2 h0 = __floats2half2_rn(r0, r1);
            __half2 h1 = __floats2half2_rn(r2, r3);
            __half2 h2 = __floats2half2_rn(r4, r5);
            __half2 h3 = __floats2half2_rn(r6, r7);
            uint4 o;
            o.x = *reinterpret_cast<uint32_t*>(&h0);
            o.y = *reinterpret_cast<uint32_t*>(&h1);
            o.z = *reinterpret_cast<uint32_t*>(&h2);
            o.w = *reinterpret_cast<uint32_t*>(&h3);
            reinterpret_cast<uint4*>(g_H + (size_t)n * 128)[l] = o;
        } else {
            float accA[4] = {0,0,0,0};
            float accB[4] = {0,0,0,0};
            for (int e = beg; e < pend; e += 8) {
                const int4 i0 = __ldg(reinterpret_cast<const int4*>(&g_csr_src[e]));
                const int4 i1 = __ldg(reinterpret_cast<const int4*>(&g_csr_src[e + 4]));
                const int idx[8] = {i0.x, i0.y, i0.z, i0.w, i1.x, i1.y, i1.z, i1.w};
                uint2 raw[8];
#pragma unroll
                for (int m = 0; m < 8; m++)
                    raw[m] = reinterpret_cast<const uint2*>(g_G + (size_t)idx[m] * 64)[l];
#pragma unroll
                for (int m = 0; m < 8; m++) {
                    float* acc = (m & 1) ? accB : accA;
                    const float2 p0 = __half22float2(*reinterpret_cast<const __half2*>(&raw[m].x));
                    const float2 p1 = __half22float2(*reinterpret_cast<const __half2*>(&raw[m].y));
                    acc[0] += p0.x; acc[1] += p0.y; acc[2] += p1.x; acc[3] += p1.y;
                }
            }
            const float ni = g_norm_in[n];
            const float4 bb = reinterpret_cast<const float4*>(bias)[l];
            float4 o;
            o.x = fmaf(accA[0] + accB[0], ni, bb.x);
            o.y = fmaf(accA[1] + accB[1], ni, bb.y);
            o.z = fmaf(accA[2] + accB[2], ni, bb.z);
            o.w = fmaf(accA[3] + accB[3], ni, bb.w);
            reinterpret_cast<float4*>(outp + (size_t)n * 64)[l] = o;
        }
    }
}

// ---------------- launch ----------------
extern "C" void kernel_launch(void* const* d_in, const int* in_sizes, int n_in,
                              void* d_out, int out_size) {
    const float* feat = (const float*)d_in[0];
    const int*   src  = (const int*)d_in[1];
    const int*   dst  = (const int*)d_in[2];
    const float* W0   = (const float*)d_in[3];
    const float* b0   = (const float*)d_in[4];
    const float* W1   = (const float*)d_in[5];
    const float* b1   = (const float*)d_in[6];
    const float* W2   = (const float*)d_in[7];
    const float* b2   = (const float*)d_in[8];
    float* out = (float*)d_out;

    const int SM128 = (128 * 68 + 2 * 64 * 68) * 4;  // 69632 B
    const int SM64  = (64 * 68 + 2 * 64 * 68) * 4;   // 52224 B
    cudaFuncSetAttribute(mma_gemm<128>, cudaFuncAttributeMaxDynamicSharedMemorySize, SM128);
    cudaFuncSetAttribute(mma_gemm<64>,  cudaFuncAttributeMaxDynamicSharedMemorySize, SM64);

    const int T = 256;
    const int GGRID = 444;   // 3 CTAs/SM
    const int AGRID = 1184;

    // 1-3: histogram, norms + feat conversion
    zero_kernel<<<(NN + T - 1) / T, T>>>();
    hist_kernel<<<(NE + T - 1) / T, T>>>(src, dst);
    norm_conv_kernel<<<(NN * 32 + T - 1) / T, T>>>(feat);
    // 4: layer-0 GEMM (profiled slot)
    mma_gemm<128><<<GGRID, T, SM128>>>(W0);
    // 5-9: padded CSR build
    fill_kernel<<<(CSR_CAP / 4 + T - 1) / T, T>>>();
    scan1_kernel<<<NBLK_SCAN, 256>>>();
    scan2_kernel<<<1, 256>>>();
    scan3_kernel<<<(NN + T - 1) / T, T>>>();
    place_kernel<<<(NE + T - 1) / T, T>>>(src, dst);

    // layer 0 aggregation -> g_H
    agg_kernel<128, false><<<AGRID, T>>>(b0, nullptr);

    // layer 1
    mma_gemm<128><<<GGRID, T, SM128>>>(W1);
    agg_kernel<128, false><<<AGRID, T>>>(b1, nullptr);

    // layer 2 (64-wide)
    mma_gemm<64><<<GGRID, T, SM64>>>(W2);
    agg_kernel<64, true><<<AGRID, T>>>(b2, out);
}